// round 12
// baseline (speedup 1.0000x reference)
#include <cuda_runtime.h>
#include <cstdint>

// Problem constants (fixed shapes)
#define B        16
#define T        4096
#define D4       128          // float4 per embedding row (512 floats)
#define KN       1024         // max_nodes
#define KE       2048         // max_edges
#define NODE_ROWS (B * KN * 2)           // 32768
#define NODE_SLOTS (B * KN)              // 16384
#define EDGE_SLOTS (B * KE)              // 32768
#define TOTAL_SLOTS (NODE_SLOTS + EDGE_SLOTS)

// Scratch: compacted positions per batch (device globals, no allocation)
__device__ int g_node_pos[NODE_SLOTS];
__device__ int g_edge_pos[EDGE_SLOTS];

// ---------------------------------------------------------------------------
// Kernel 1: per-batch dual stream compaction (routing==0 -> nodes,
// routing==1 -> edges). One block per batch, 1024 threads, 4 elems/thread.
// Fires the PDL trigger after its scatters so the gather grid can launch.
// ---------------------------------------------------------------------------
__global__ void compact_kernel(const int* __restrict__ routing) {
    const int b    = blockIdx.x;
    const int tid  = threadIdx.x;          // 0..1023
    const int lane = tid & 31;
    const int wid  = tid >> 5;

    // Reset scratch for determinism across graph replays.
    g_node_pos[b * KN + tid] = -1;
    g_edge_pos[b * KE + tid] = -1;
    g_edge_pos[b * KE + 1024 + tid] = -1;

    const int4 rv = reinterpret_cast<const int4*>(routing + (size_t)b * T)[tid];
    int v[4] = { rv.x, rv.y, rv.z, rv.w };

    int c0 = 0, c1 = 0;
#pragma unroll
    for (int i = 0; i < 4; i++) { c0 += (v[i] == 0); c1 += (v[i] == 1); }
    const int packed = c0 | (c1 << 16);

    // Warp inclusive scan (zeros in low 16 bits, ones in high 16)
    int x = packed;
#pragma unroll
    for (int off = 1; off < 32; off <<= 1) {
        int y = __shfl_up_sync(0xffffffffu, x, off);
        if (lane >= off) x += y;
    }

    __shared__ int warp_sums[32];
    if (lane == 31) warp_sums[wid] = x;
    __syncthreads();

    if (wid == 0) {
        int w = warp_sums[lane];
#pragma unroll
        for (int off = 1; off < 32; off <<= 1) {
            int y = __shfl_up_sync(0xffffffffu, w, off);
            if (lane >= off) w += y;
        }
        warp_sums[lane] = w;
    }
    __syncthreads();

    const int incl = x + (wid > 0 ? warp_sums[wid - 1] : 0);
    const int excl = incl - packed;
    int idx0 = excl & 0xffff;
    int idx1 = excl >> 16;

    const int t0 = tid * 4;
#pragma unroll
    for (int i = 0; i < 4; i++) {
        const int val = v[i];
        if (val == 0) {
            if (idx0 < KN) g_node_pos[b * KN + idx0] = t0 + i;
            idx0++;
        } else if (val == 1) {
            if (idx1 < KE) g_edge_pos[b * KE + idx1] = t0 + i;
            idx1++;
        }
    }

    // Allow the dependent gather grid to begin launching.
    cudaTriggerProgrammaticLaunchCompletion();
}

// ---------------------------------------------------------------------------
// Kernel 2: gather with repeat-aware streaming (.cs) stores.
// One 128-thread block per SOURCE SLOT. Each thread loads one float4 of the
// 2KB embedding row once, then stores it to all repeat destinations
// (2x node, 5x edge). PDL: index math happens before the dependency sync.
// Output layout: node_pe [B,2048,512] flat, then edge_pe [B,10240,512] flat.
// ---------------------------------------------------------------------------
__global__ void gather_kernel(const float4* __restrict__ pe,
                              float4* __restrict__ out) {
    const int slot = blockIdx.x;
    const int t = threadIdx.x;

    // Pre-sync work: compute destination addressing.
    const bool is_node = (slot < NODE_SLOTS);
    const int  es      = slot - NODE_SLOTS;
    float4* dst = is_node
        ? out + ((size_t)slot * 2) * D4 + t
        : out + ((size_t)NODE_ROWS + (size_t)es * 5) * D4 + t;

    // Wait for compact_kernel's results to be visible.
    cudaGridDependencySynchronize();

    if (is_node) {
        int pos = g_node_pos[slot];
        if (pos < 0) pos = 0;
        const float4 v = __ldg(pe + (size_t)pos * D4 + t);
        __stcs(dst,          v);
        __stcs(dst + 1 * D4, v);
    } else {
        int pos = g_edge_pos[es];
        if (pos < 0) pos = 0;
        const float4 v = __ldg(pe + (size_t)pos * D4 + t);
        __stcs(dst,          v);
        __stcs(dst + 1 * D4, v);
        __stcs(dst + 2 * D4, v);
        __stcs(dst + 3 * D4, v);
        __stcs(dst + 4 * D4, v);
    }
}

// ---------------------------------------------------------------------------
// Inputs (metadata order):
//   d_in[0] routing  (int32, B*T)
//   d_in[1] max_nodes (scalar, fixed 1024)
//   d_in[2] max_edges (scalar, fixed 2048)
//   d_in[3] pos_embed (float32, T*512)
// d_out: float32, node_pe then edge_pe, flat.
// ---------------------------------------------------------------------------
extern "C" void kernel_launch(void* const* d_in, const int* in_sizes, int n_in,
                              void* d_out, int out_size) {
    const int*    routing = (const int*)d_in[0];
    const float4* pe      = (const float4*)d_in[3];
    float4*       out     = (float4*)d_out;

    compact_kernel<<<B, 1024>>>(routing);

    // Launch gather with programmatic dependent launch so its blocks can
    // spin up while compact_kernel drains.
    cudaLaunchConfig_t cfg = {};
    cfg.gridDim  = dim3(TOTAL_SLOTS, 1, 1);
    cfg.blockDim = dim3(128, 1, 1);
    cfg.dynamicSmemBytes = 0;
    cfg.stream = 0;
    cudaLaunchAttribute attrs[1];
    attrs[0].id = cudaLaunchAttributeProgrammaticStreamSerialization;
    attrs[0].val.programmaticStreamSerializationAllowed = 1;
    cfg.attrs = attrs;
    cfg.numAttrs = 1;
    cudaLaunchKernelEx(&cfg, gather_kernel, pe, out);
}

// round 13
// speedup vs baseline: 1.0183x; 1.0183x over previous
#include <cuda_runtime.h>
#include <cstdint>

// Problem constants (fixed shapes)
#define B        16
#define T        4096
#define D4       128          // float4 per embedding row (512 floats)
#define KN       1024         // max_nodes
#define KE       2048         // max_edges
#define NODE_ROWS (B * KN * 2)           // 32768
#define NODE_SLOTS (B * KN)              // 16384
#define EDGE_SLOTS (B * KE)              // 32768
#define TOTAL_SLOTS (NODE_SLOTS + EDGE_SLOTS)

// Scratch: compacted positions per batch (device globals, no allocation)
__device__ int g_node_pos[NODE_SLOTS];
__device__ int g_edge_pos[EDGE_SLOTS];

// ---------------------------------------------------------------------------
// Kernel 1: per-batch dual stream compaction (routing==0 -> nodes,
// routing==1 -> edges). One block per batch, 1024 threads, 4 elems/thread.
// Fires the PDL trigger after its scatters so the gather grid can launch.
// ---------------------------------------------------------------------------
__global__ void compact_kernel(const int* __restrict__ routing) {
    const int b    = blockIdx.x;
    const int tid  = threadIdx.x;          // 0..1023
    const int lane = tid & 31;
    const int wid  = tid >> 5;

    // Reset scratch for determinism across graph replays.
    g_node_pos[b * KN + tid] = -1;
    g_edge_pos[b * KE + tid] = -1;
    g_edge_pos[b * KE + 1024 + tid] = -1;

    const int4 rv = reinterpret_cast<const int4*>(routing + (size_t)b * T)[tid];
    int v[4] = { rv.x, rv.y, rv.z, rv.w };

    int c0 = 0, c1 = 0;
#pragma unroll
    for (int i = 0; i < 4; i++) { c0 += (v[i] == 0); c1 += (v[i] == 1); }
    const int packed = c0 | (c1 << 16);

    // Warp inclusive scan (zeros in low 16 bits, ones in high 16)
    int x = packed;
#pragma unroll
    for (int off = 1; off < 32; off <<= 1) {
        int y = __shfl_up_sync(0xffffffffu, x, off);
        if (lane >= off) x += y;
    }

    __shared__ int warp_sums[32];
    if (lane == 31) warp_sums[wid] = x;
    __syncthreads();

    if (wid == 0) {
        int w = warp_sums[lane];
#pragma unroll
        for (int off = 1; off < 32; off <<= 1) {
            int y = __shfl_up_sync(0xffffffffu, w, off);
            if (lane >= off) w += y;
        }
        warp_sums[lane] = w;
    }
    __syncthreads();

    const int incl = x + (wid > 0 ? warp_sums[wid - 1] : 0);
    const int excl = incl - packed;
    int idx0 = excl & 0xffff;
    int idx1 = excl >> 16;

    const int t0 = tid * 4;
#pragma unroll
    for (int i = 0; i < 4; i++) {
        const int val = v[i];
        if (val == 0) {
            if (idx0 < KN) g_node_pos[b * KN + idx0] = t0 + i;
            idx0++;
        } else if (val == 1) {
            if (idx1 < KE) g_edge_pos[b * KE + idx1] = t0 + i;
            idx1++;
        }
    }

    // Allow the dependent gather grid to begin launching.
    cudaTriggerProgrammaticLaunchCompletion();
}

// ---------------------------------------------------------------------------
// Kernel 2: gather with repeat-aware streaming (.cs) stores.
// One 128-thread block per SOURCE SLOT. Each thread loads one float4 of the
// 2KB embedding row once, then stores it to all repeat destinations
// (2x node, 5x edge). PDL: index math happens before the dependency sync.
// Output layout: node_pe [B,2048,512] flat, then edge_pe [B,10240,512] flat.
// ---------------------------------------------------------------------------
__global__ void gather_kernel(const float4* __restrict__ pe,
                              float4* __restrict__ out) {
    const int slot = blockIdx.x;
    const int t = threadIdx.x;

    // Pre-sync work: compute destination addressing.
    const bool is_node = (slot < NODE_SLOTS);
    const int  es      = slot - NODE_SLOTS;
    float4* dst = is_node
        ? out + ((size_t)slot * 2) * D4 + t
        : out + ((size_t)NODE_ROWS + (size_t)es * 5) * D4 + t;

    // Wait for compact_kernel's results to be visible.
    cudaGridDependencySynchronize();

    if (is_node) {
        int pos = g_node_pos[slot];
        if (pos < 0) pos = 0;
        const float4 v = __ldg(pe + (size_t)pos * D4 + t);
        __stcs(dst,          v);
        __stcs(dst + 1 * D4, v);
    } else {
        int pos = g_edge_pos[es];
        if (pos < 0) pos = 0;
        const float4 v = __ldg(pe + (size_t)pos * D4 + t);
        __stcs(dst,          v);
        __stcs(dst + 1 * D4, v);
        __stcs(dst + 2 * D4, v);
        __stcs(dst + 3 * D4, v);
        __stcs(dst + 4 * D4, v);
    }
}

// ---------------------------------------------------------------------------
// Inputs (metadata order):
//   d_in[0] routing  (int32, B*T)
//   d_in[1] max_nodes (scalar, fixed 1024)
//   d_in[2] max_edges (scalar, fixed 2048)
//   d_in[3] pos_embed (float32, T*512)
// d_out: float32, node_pe then edge_pe, flat.
// ---------------------------------------------------------------------------
extern "C" void kernel_launch(void* const* d_in, const int* in_sizes, int n_in,
                              void* d_out, int out_size) {
    const int*    routing = (const int*)d_in[0];
    const float4* pe      = (const float4*)d_in[3];
    float4*       out     = (float4*)d_out;

    compact_kernel<<<B, 1024>>>(routing);

    // Launch gather with programmatic dependent launch so its blocks can
    // spin up while compact_kernel drains.
    cudaLaunchConfig_t cfg = {};
    cfg.gridDim  = dim3(TOTAL_SLOTS, 1, 1);
    cfg.blockDim = dim3(128, 1, 1);
    cfg.dynamicSmemBytes = 0;
    cfg.stream = 0;
    cudaLaunchAttribute attrs[1];
    attrs[0].id = cudaLaunchAttributeProgrammaticStreamSerialization;
    attrs[0].val.programmaticStreamSerializationAllowed = 1;
    cfg.attrs = attrs;
    cfg.numAttrs = 1;
    cudaLaunchKernelEx(&cfg, gather_kernel, pe, out);
}